// round 12
// baseline (speedup 1.0000x reference)
#include <cuda_runtime.h>
#include <cstdint>

// Problem constants
#define BB   128        // batch
#define IN_  1024
#define OUT_ 1024
#define NS   16         // i-dimension splits (empirical optimum)
#define LI   (IN_/NS)   // 64 i-values per split
#define NB   8          // batches per block (amortization sweet spot)
#define NBG  (BB/NB)    // 16 batch groups
#define OT   256        // outs per block
#define OTG  (OUT_/OT)  // 4 out groups
#define O4   (OUT_/4)   // 256 float4 lanes over full OUT
#define OT4  (OT/4)     // 64 float4 lanes per block

// ---------------------------------------------------------------------------
// Single fused kernel. The proven-fastest streaming loop (NS=16, NB=8,
// OT=256, 128 threads, occ 7 — 1024 blocks) with the epilogue changed from
// partial-store to DIRECT scattered atomicAdd into out (pre-zeroed by a
// memset node). This removes the 8MB partial write + 8MB read AND the
// second kernel, whose 5.5us cost was shown (R9-R11) to be a structural
// floor: DRAM-latency-bound re-fetch of evicted partials + launch ramp,
// immune to layout (R10) and PDL (R11). Atomic contention is negligible:
// each address receives 16 adds spread over ~80us from staggered block
// epilogues. FP ordering varies ~1e-7 per replay, well inside 1e-3.
// softplus(ro) fused; bias folded into s==0 contributions; eps via __ldcs.
// ---------------------------------------------------------------------------
__global__ __launch_bounds__(128, 7)
void main_kernel(const float* __restrict__ x,
                 const float* __restrict__ mu,
                 const float* __restrict__ ro,
                 const float* __restrict__ eps,
                 const float* __restrict__ mu_bias,
                 const float* __restrict__ ro_bias,
                 const float* __restrict__ eps_bias,
                 float* __restrict__ out) {
    __shared__ float xs[NB][LI];          // 2 KB

    const int bx = blockIdx.x;            // 0..1023
    const int s  = bx & (NS - 1);         // 0..15
    const int bg = (bx >> 4) & (NBG - 1); // 0..15
    const int z  = bx >> 8;               // 0..3
    const int t  = threadIdx.x;
    const int l  = t & (OT4 - 1);         // o float4 lane (0..63)
    const int g  = t >> 6;                // 0..1 batch class
    const int i0 = s * LI;
    const int b0 = bg * NB;
    const int oc = z * OT4 + l;           // float4 column in [0, O4)

    // Cooperative float4 load of x tile [8 b][64 i]: 128 float4s, one each
    {
        const int row = t >> 4;           // 0..7
        const int col = (t & 15) * 4;     // 0..60
        float4 v = *reinterpret_cast<const float4*>(
            x + (size_t)(b0 + row) * IN_ + i0 + col);
        *reinterpret_cast<float4*>(&xs[row][col]) = v;
    }
    __syncthreads();

    const float4* mu4 = reinterpret_cast<const float4*>(mu)  + (size_t)i0 * O4 + oc;
    const float4* ro4 = reinterpret_cast<const float4*>(ro)  + (size_t)i0 * O4 + oc;
    const float4* ep4 = reinterpret_cast<const float4*>(eps)
                        + ((size_t)b0 * IN_ + i0) * O4 + oc;

    float4 acc[4];

    // ---- ii = 0 peeled: pure multiply (initializes acc) ----
    {
        float4 ev[4];
#pragma unroll
        for (int k = 0; k < 4; k++) {
            const int lb = g + 2 * k;
            ev[k] = __ldcs(&ep4[(size_t)lb * IN_ * O4]);
        }
        const float4 rr = ro4[0];
        const float4 mw = mu4[0];
        float4 sg;
        sg.x = log1pf(__expf(rr.x));
        sg.y = log1pf(__expf(rr.y));
        sg.z = log1pf(__expf(rr.z));
        sg.w = log1pf(__expf(rr.w));
#pragma unroll
        for (int k = 0; k < 4; k++) {
            const int lb = g + 2 * k;
            const float xr = xs[lb][0];
            acc[k].x = xr * fmaf(ev[k].x, sg.x, mw.x);
            acc[k].y = xr * fmaf(ev[k].y, sg.y, mw.y);
            acc[k].z = xr * fmaf(ev[k].z, sg.z, mw.z);
            acc[k].w = xr * fmaf(ev[k].w, sg.w, mw.w);
        }
    }

    // ---- ii = 1 .. LI-1 ----
#pragma unroll 1
    for (int ii = 1; ii < LI; ii++) {
        float4 ev[4];
#pragma unroll
        for (int k = 0; k < 4; k++) {
            const int lb = g + 2 * k;
            ev[k] = __ldcs(&ep4[((size_t)lb * IN_ + ii) * O4]);
        }
        const float4 rr = ro4[(size_t)ii * O4];
        const float4 mw = mu4[(size_t)ii * O4];
        float4 sg;
        sg.x = log1pf(__expf(rr.x));
        sg.y = log1pf(__expf(rr.y));
        sg.z = log1pf(__expf(rr.z));
        sg.w = log1pf(__expf(rr.w));
#pragma unroll
        for (int k = 0; k < 4; k++) {
            const int lb = g + 2 * k;
            const float xr = xs[lb][ii];
            acc[k].x = fmaf(xr, fmaf(ev[k].x, sg.x, mw.x), acc[k].x);
            acc[k].y = fmaf(xr, fmaf(ev[k].y, sg.y, mw.y), acc[k].y);
            acc[k].z = fmaf(xr, fmaf(ev[k].z, sg.z, mw.z), acc[k].z);
            acc[k].w = fmaf(xr, fmaf(ev[k].w, sg.w, mw.w), acc[k].w);
        }
    }

    // ---- s==0 blocks fold in the bias term ----
    if (s == 0) {
        const float4 rb = reinterpret_cast<const float4*>(ro_bias)[oc];
        const float4 mb = reinterpret_cast<const float4*>(mu_bias)[oc];
        float4 sb;
        sb.x = log1pf(__expf(rb.x));
        sb.y = log1pf(__expf(rb.y));
        sb.z = log1pf(__expf(rb.z));
        sb.w = log1pf(__expf(rb.w));
#pragma unroll
        for (int k = 0; k < 4; k++) {
            const int lb = g + 2 * k;
            const float4 eb = reinterpret_cast<const float4*>(eps_bias)
                                  [(size_t)(b0 + lb) * O4 + oc];
            acc[k].x = fmaf(eb.x, sb.x, acc[k].x + mb.x);
            acc[k].y = fmaf(eb.y, sb.y, acc[k].y + mb.y);
            acc[k].z = fmaf(eb.z, sb.z, acc[k].z + mb.z);
            acc[k].w = fmaf(eb.w, sb.w, acc[k].w + mb.w);
        }
    }

    // ---- scattered atomic accumulation into out (pre-zeroed) ----
#pragma unroll
    for (int k = 0; k < 4; k++) {
        const int lb = g + 2 * k;
        float* op = out + (size_t)(b0 + lb) * OUT_ + oc * 4;
        atomicAdd(op + 0, acc[k].x);
        atomicAdd(op + 1, acc[k].y);
        atomicAdd(op + 2, acc[k].z);
        atomicAdd(op + 3, acc[k].w);
    }
}

// ---------------------------------------------------------------------------
// Launch. Input order (metadata): x, mu, ro, mu_bias, ro_bias, eps, eps_bias
// ---------------------------------------------------------------------------
extern "C" void kernel_launch(void* const* d_in, const int* in_sizes, int n_in,
                              void* d_out, int out_size) {
    const float* x        = (const float*)d_in[0];
    const float* mu       = (const float*)d_in[1];
    const float* ro       = (const float*)d_in[2];
    const float* mu_bias  = (const float*)d_in[3];
    const float* ro_bias  = (const float*)d_in[4];
    const float* eps      = (const float*)d_in[5];
    const float* eps_bias = (const float*)d_in[6];
    float* out = (float*)d_out;

    // Zero the output (graph-capturable memset node; fp32 zero == 0x0).
    cudaMemsetAsync(out, 0, (size_t)out_size * sizeof(float), 0);

    // Single fused kernel: 1024 blocks x 128 threads, occ 7
    main_kernel<<<NS * NBG * OTG, 128>>>(x, mu, ro, eps,
                                         mu_bias, ro_bias, eps_bias, out);
}

// round 14
// speedup vs baseline: 1.0044x; 1.0044x over previous
#include <cuda_runtime.h>
#include <cstdint>

// Problem constants
#define BB   128        // batch
#define IN_  1024
#define OUT_ 1024
#define NS   16         // i-dimension splits (empirical optimum)
#define LI   (IN_/NS)   // 64 i-values per split
#define NB   8          // batches per block (amortization sweet spot)
#define NBG  (BB/NB)    // 16 batch groups
#define OT   256        // outs per block
#define OTG  (OUT_/OT)  // 4 out groups
#define O4   (OUT_/4)   // 256 float4 lanes over full OUT
#define OT4  (OT/4)     // 64 float4 lanes per block

// Scratch (allocation-free rule: __device__ global)
__device__ float g_partial[NS * BB * OUT_];   // per-split partials, 8 MB

// L2 evict-last store via the cache-policy-register form (the static
// .L2::evict_last qualifier is only legal on 256-bit stores on sm_103;
// createpolicy + cache_hint works for v4.f32). Keeps the 8MB partial
// buffer resident in the 126MB L2 while the ~500MB eps stream flows past —
// R9-R11 profiles showed the reduce re-reading ALL partials from DRAM.
__device__ __forceinline__ uint64_t mk_evict_last_policy() {
    uint64_t pol;
    asm volatile("createpolicy.fractional.L2::evict_last.b64 %0, 1.0;"
                 : "=l"(pol));
    return pol;
}

__device__ __forceinline__ void st_policy(float4* p, float4 v, uint64_t pol) {
    asm volatile("st.global.L2::cache_hint.v4.f32 [%0], {%1,%2,%3,%4}, %5;"
                 :: "l"(p), "f"(v.x), "f"(v.y), "f"(v.z), "f"(v.w), "l"(pol)
                 : "memory");
}

__device__ __forceinline__ uint64_t mk_evict_first_policy() {
    uint64_t pol;
    asm volatile("createpolicy.fractional.L2::evict_first.b64 %0, 1.0;"
                 : "=l"(pol));
    return pol;
}

__device__ __forceinline__ float4 ld_policy(const float4* p, uint64_t pol) {
    float4 v;
    asm volatile("ld.global.L2::cache_hint.v4.f32 {%0,%1,%2,%3}, [%4], %5;"
                 : "=f"(v.x), "=f"(v.y), "=f"(v.z), "=f"(v.w)
                 : "l"(p), "l"(pol));
    return v;
}

// ---------------------------------------------------------------------------
// Main streaming kernel — R9's proven-fastest config (main ~81us): 1024
// blocks of 128 threads, occ 7. Block (s,bg,z): i in [s*LI,(s+1)*LI),
// batches [bg*8,bg*8+8), outs [z*256,z*256+256). acc[4] float4/thread.
// x staged via 2KB smem. softplus(ro) fused; bias folded into s==0 partials;
// eps via __ldcs (evict-first). ONLY change vs R9: partial stores carry an
// evict-last L2 policy so the reduce kernel hits L2 instead of DRAM.
// ---------------------------------------------------------------------------
__global__ __launch_bounds__(128, 7)
void main_kernel(const float* __restrict__ x,
                 const float* __restrict__ mu,
                 const float* __restrict__ ro,
                 const float* __restrict__ eps,
                 const float* __restrict__ mu_bias,
                 const float* __restrict__ ro_bias,
                 const float* __restrict__ eps_bias) {
    __shared__ float xs[NB][LI];          // 2 KB

    const int bx = blockIdx.x;            // 0..1023
    const int s  = bx & (NS - 1);         // 0..15
    const int bg = (bx >> 4) & (NBG - 1); // 0..15
    const int z  = bx >> 8;               // 0..3
    const int t  = threadIdx.x;
    const int l  = t & (OT4 - 1);         // o float4 lane (0..63)
    const int g  = t >> 6;                // 0..1 batch class
    const int i0 = s * LI;
    const int b0 = bg * NB;
    const int oc = z * OT4 + l;           // float4 column in [0, O4)

    // Cooperative float4 load of x tile [8 b][64 i]: 128 float4s, one each
    {
        const int row = t >> 4;           // 0..7
        const int col = (t & 15) * 4;     // 0..60
        float4 v = *reinterpret_cast<const float4*>(
            x + (size_t)(b0 + row) * IN_ + i0 + col);
        *reinterpret_cast<float4*>(&xs[row][col]) = v;
    }
    __syncthreads();

    const float4* mu4 = reinterpret_cast<const float4*>(mu)  + (size_t)i0 * O4 + oc;
    const float4* ro4 = reinterpret_cast<const float4*>(ro)  + (size_t)i0 * O4 + oc;
    const float4* ep4 = reinterpret_cast<const float4*>(eps)
                        + ((size_t)b0 * IN_ + i0) * O4 + oc;

    float4 acc[4];

    // ---- ii = 0 peeled: pure multiply (initializes acc) ----
    {
        float4 ev[4];
#pragma unroll
        for (int k = 0; k < 4; k++) {
            const int lb = g + 2 * k;
            ev[k] = __ldcs(&ep4[(size_t)lb * IN_ * O4]);
        }
        const float4 rr = ro4[0];
        const float4 mw = mu4[0];
        float4 sg;
        sg.x = log1pf(__expf(rr.x));
        sg.y = log1pf(__expf(rr.y));
        sg.z = log1pf(__expf(rr.z));
        sg.w = log1pf(__expf(rr.w));
#pragma unroll
        for (int k = 0; k < 4; k++) {
            const int lb = g + 2 * k;
            const float xr = xs[lb][0];
            acc[k].x = xr * fmaf(ev[k].x, sg.x, mw.x);
            acc[k].y = xr * fmaf(ev[k].y, sg.y, mw.y);
            acc[k].z = xr * fmaf(ev[k].z, sg.z, mw.z);
            acc[k].w = xr * fmaf(ev[k].w, sg.w, mw.w);
        }
    }

    // ---- ii = 1 .. LI-1 ----
#pragma unroll 1
    for (int ii = 1; ii < LI; ii++) {
        float4 ev[4];
#pragma unroll
        for (int k = 0; k < 4; k++) {
            const int lb = g + 2 * k;
            ev[k] = __ldcs(&ep4[((size_t)lb * IN_ + ii) * O4]);
        }
        const float4 rr = ro4[(size_t)ii * O4];
        const float4 mw = mu4[(size_t)ii * O4];
        float4 sg;
        sg.x = log1pf(__expf(rr.x));
        sg.y = log1pf(__expf(rr.y));
        sg.z = log1pf(__expf(rr.z));
        sg.w = log1pf(__expf(rr.w));
#pragma unroll
        for (int k = 0; k < 4; k++) {
            const int lb = g + 2 * k;
            const float xr = xs[lb][ii];
            acc[k].x = fmaf(xr, fmaf(ev[k].x, sg.x, mw.x), acc[k].x);
            acc[k].y = fmaf(xr, fmaf(ev[k].y, sg.y, mw.y), acc[k].y);
            acc[k].z = fmaf(xr, fmaf(ev[k].z, sg.z, mw.z), acc[k].z);
            acc[k].w = fmaf(xr, fmaf(ev[k].w, sg.w, mw.w), acc[k].w);
        }
    }

    // ---- s==0 blocks fold in the bias term ----
    if (s == 0) {
        const float4 rb = reinterpret_cast<const float4*>(ro_bias)[oc];
        const float4 mb = reinterpret_cast<const float4*>(mu_bias)[oc];
        float4 sb;
        sb.x = log1pf(__expf(rb.x));
        sb.y = log1pf(__expf(rb.y));
        sb.z = log1pf(__expf(rb.z));
        sb.w = log1pf(__expf(rb.w));
#pragma unroll
        for (int k = 0; k < 4; k++) {
            const int lb = g + 2 * k;
            const float4 eb = reinterpret_cast<const float4*>(eps_bias)
                                  [(size_t)(b0 + lb) * O4 + oc];
            acc[k].x = fmaf(eb.x, sb.x, acc[k].x + mb.x);
            acc[k].y = fmaf(eb.y, sb.y, acc[k].y + mb.y);
            acc[k].z = fmaf(eb.z, sb.z, acc[k].z + mb.z);
            acc[k].w = fmaf(eb.w, sb.w, acc[k].w + mb.w);
        }
    }

    // ---- write partials P[s][b][o] with evict-last policy (coalesced) ----
    const uint64_t pol = mk_evict_last_policy();
    float4* Pbase = reinterpret_cast<float4*>(g_partial);
#pragma unroll
    for (int k = 0; k < 4; k++) {
        const int lb = g + 2 * k;
        st_policy(&Pbase[((size_t)s * BB + b0 + lb) * O4 + oc], acc[k], pol);
    }
}

// ---------------------------------------------------------------------------
// Reduce: 4-way-split s-sum (R9 structure, measured best). With partials
// L2-resident (evict-last stores), the latency-bound load phase runs at L2
// latency instead of DRAM; loads carry evict-first (read-once). Thread
// (q=t>>5, lane=t&31) sums partials s in [4q,4q+4) for output lane L,
// quarters combine via smem in fixed q-order (deterministic).
// ---------------------------------------------------------------------------
__global__ __launch_bounds__(128)
void reduce_kernel(float* __restrict__ out) {
    __shared__ float4 red[4][32];

    const int t    = threadIdx.x;
    const int lane = t & 31;
    const int q    = t >> 5;                       // 0..3
    const int L    = blockIdx.x * 32 + lane;       // 0..BB*O4-1

    const uint64_t pol = mk_evict_first_policy();
    const float4* Pc = reinterpret_cast<const float4*>(g_partial) + L;

    // Fixed ascending order within quarter
    float4 r = ld_policy(&Pc[(size_t)(q * 4) * BB * O4], pol);
#pragma unroll
    for (int j = 1; j < 4; j++) {
        float4 p = ld_policy(&Pc[(size_t)(q * 4 + j) * BB * O4], pol);
        r.x += p.x; r.y += p.y; r.z += p.z; r.w += p.w;
    }
    red[q][lane] = r;
    __syncthreads();

    if (q == 0) {
        // Fixed quarter order -> deterministic
        float4 a = red[0][lane];
#pragma unroll
        for (int j = 1; j < 4; j++) {
            float4 p = red[j][lane];
            a.x += p.x; a.y += p.y; a.z += p.z; a.w += p.w;
        }
        reinterpret_cast<float4*>(out)[L] = a;
    }
}

// ---------------------------------------------------------------------------
// Launch. Input order (metadata): x, mu, ro, mu_bias, ro_bias, eps, eps_bias
// ---------------------------------------------------------------------------
extern "C" void kernel_launch(void* const* d_in, const int* in_sizes, int n_in,
                              void* d_out, int out_size) {
    const float* x        = (const float*)d_in[0];
    const float* mu       = (const float*)d_in[1];
    const float* ro       = (const float*)d_in[2];
    const float* mu_bias  = (const float*)d_in[3];
    const float* ro_bias  = (const float*)d_in[4];
    const float* eps      = (const float*)d_in[5];
    const float* eps_bias = (const float*)d_in[6];
    float* out = (float*)d_out;

    // Main: 1024 blocks x 128 threads, occ 7 (proven fastest streaming loop)
    main_kernel<<<NS * NBG * OTG, 128>>>(x, mu, ro, eps,
                                         mu_bias, ro_bias, eps_bias);

    // Reduce: 1024 blocks x 128 threads (4-way split s-sum)
    reduce_kernel<<<(BB * O4) / 32, 128>>>(out);
}

// round 15
// speedup vs baseline: 1.0241x; 1.0196x over previous
#include <cuda_runtime.h>
#include <cstdint>

// Problem constants
#define BB   128        // batch
#define IN_  1024
#define OUT_ 1024
#define NS   16         // i-dimension splits (empirical optimum)
#define LI   (IN_/NS)   // 64 i-values per split
#define NB   8          // batches per block (amortization sweet spot)
#define NBG  (BB/NB)    // 16 batch groups
#define OT   256        // outs per block
#define OTG  (OUT_/OT)  // 4 out groups
#define O4   (OUT_/4)   // 256 float4 lanes over full OUT
#define OT4  (OT/4)     // 64 float4 lanes per block
#define NTILE (NBG*OTG) // 64 (bg,z) tiles
#define NMAIN (NS*NTILE)// 1024 streaming blocks
#define NRED  1024      // reducer blocks (16 per tile)

// Scratch (allocation-free rule: __device__ globals; zero-init, self-reset)
__device__ float g_partial[NS * BB * OUT_];   // per-split partials, 8 MB
__device__ int   g_count[NTILE];              // producer arrivals per tile
__device__ int   g_done[NTILE];               // reducer completions per tile

// ---------------------------------------------------------------------------
// Single kernel, two roles by blockIdx:
//   bx <  NMAIN: R9's proven streaming block (s,bg,z) — untouched inner loop.
//   bx >= NMAIN: reducer block — spins (nanosleep) until its tile's 16
//                producers have arrived, then does a 32-float4 slice of the
//                4-way-split s-sum (R9 reduce shape, fixed order).
// Why: the 5.5us reduce floor (R9-R14: immune to layout/PDL/atomics/policy)
// is hidden under the streaming drain tail. Wave 1 = 148*7 = 1036 slots =
// ALL 1024 producers + 12 spinners -> deadlock-free by construction; the
// other 1012 reducers schedule as producers exit, overlapping the tail.
// Dual counters (count/done) self-reset for graph replay determinism.
// ---------------------------------------------------------------------------
__global__ __launch_bounds__(128, 7)
void fused_kernel(const float* __restrict__ x,
                  const float* __restrict__ mu,
                  const float* __restrict__ ro,
                  const float* __restrict__ eps,
                  const float* __restrict__ mu_bias,
                  const float* __restrict__ ro_bias,
                  const float* __restrict__ eps_bias,
                  float* __restrict__ out) {
    __shared__ float4 red[4][32];     // reducer combine buffer (2 KB)
    __shared__ float  xs[NB][LI];     // producer x tile (2 KB)

    const int bx = blockIdx.x;
    const int t  = threadIdx.x;

    if (bx >= NMAIN) {
        // =================== REDUCER ROLE ===================
        const int rb   = bx - NMAIN;          // 0..1023
        const int tile = rb >> 4;             // 0..63  (= bg*OTG + z)
        const int sub  = rb & 15;             // 0..15  slice of the tile
        const int bg   = tile >> 2;
        const int z    = tile & (OTG - 1);
        const int b0   = bg * NB;

        // Spin until all NS producers of this tile arrived
        if (t == 0) {
            while (atomicAdd(&g_count[tile], 0) < NS)
                __nanosleep(200);
        }
        __syncthreads();
        __threadfence();                      // acquire partials

        const int lane = t & 31;
        const int q    = t >> 5;              // 0..3 s-quarter
        // Output entry within tile: e in [0,512), this slice covers 32
        const int e    = sub * 32 + lane;
        const int lb   = e >> 6;              // 0..7 batch in tile
        const int oc   = z * OT4 + (e & 63);  // float4 column
        const size_t L = (size_t)(b0 + lb) * O4 + oc;

        const float4* Pc = reinterpret_cast<const float4*>(g_partial) + L;

        // Fixed ascending order within quarter
        float4 r = Pc[(size_t)(q * 4) * BB * O4];
#pragma unroll
        for (int j = 1; j < 4; j++) {
            float4 p = Pc[(size_t)(q * 4 + j) * BB * O4];
            r.x += p.x; r.y += p.y; r.z += p.z; r.w += p.w;
        }
        red[q][lane] = r;
        __syncthreads();

        if (q == 0) {
            // Fixed quarter order -> deterministic
            float4 a = red[0][lane];
#pragma unroll
            for (int j = 1; j < 4; j++) {
                float4 p = red[j][lane];
                a.x += p.x; a.y += p.y; a.z += p.z; a.w += p.w;
            }
            reinterpret_cast<float4*>(out)[L] = a;
        }

        // Completion + counter reset for next graph replay
        __syncthreads();
        if (t == 0) {
            int d = atomicAdd(&g_done[tile], 1);
            if (d == 15) {                    // last reducer of this tile
                atomicExch(&g_count[tile], 0);
                atomicExch(&g_done[tile], 0);
            }
        }
        return;
    }

    // =================== PRODUCER ROLE (R9 streaming loop, unchanged) ===
    const int s  = bx & (NS - 1);         // 0..15
    const int bg = (bx >> 4) & (NBG - 1); // 0..15
    const int z  = bx >> 8;               // 0..3
    const int l  = t & (OT4 - 1);         // o float4 lane (0..63)
    const int g  = t >> 6;                // 0..1 batch class
    const int i0 = s * LI;
    const int b0 = bg * NB;
    const int oc = z * OT4 + l;           // float4 column in [0, O4)

    // Cooperative float4 load of x tile [8 b][64 i]
    {
        const int row = t >> 4;           // 0..7
        const int col = (t & 15) * 4;     // 0..60
        float4 v = *reinterpret_cast<const float4*>(
            x + (size_t)(b0 + row) * IN_ + i0 + col);
        *reinterpret_cast<float4*>(&xs[row][col]) = v;
    }
    __syncthreads();

    const float4* mu4 = reinterpret_cast<const float4*>(mu)  + (size_t)i0 * O4 + oc;
    const float4* ro4 = reinterpret_cast<const float4*>(ro)  + (size_t)i0 * O4 + oc;
    const float4* ep4 = reinterpret_cast<const float4*>(eps)
                        + ((size_t)b0 * IN_ + i0) * O4 + oc;

    float4 acc[4];

    // ---- ii = 0 peeled ----
    {
        float4 ev[4];
#pragma unroll
        for (int k = 0; k < 4; k++) {
            const int lb = g + 2 * k;
            ev[k] = __ldcs(&ep4[(size_t)lb * IN_ * O4]);
        }
        const float4 rr = ro4[0];
        const float4 mw = mu4[0];
        float4 sg;
        sg.x = log1pf(__expf(rr.x));
        sg.y = log1pf(__expf(rr.y));
        sg.z = log1pf(__expf(rr.z));
        sg.w = log1pf(__expf(rr.w));
#pragma unroll
        for (int k = 0; k < 4; k++) {
            const int lb = g + 2 * k;
            const float xr = xs[lb][0];
            acc[k].x = xr * fmaf(ev[k].x, sg.x, mw.x);
            acc[k].y = xr * fmaf(ev[k].y, sg.y, mw.y);
            acc[k].z = xr * fmaf(ev[k].z, sg.z, mw.z);
            acc[k].w = xr * fmaf(ev[k].w, sg.w, mw.w);
        }
    }

    // ---- ii = 1 .. LI-1 ----
#pragma unroll 1
    for (int ii = 1; ii < LI; ii++) {
        float4 ev[4];
#pragma unroll
        for (int k = 0; k < 4; k++) {
            const int lb = g + 2 * k;
            ev[k] = __ldcs(&ep4[((size_t)lb * IN_ + ii) * O4]);
        }
        const float4 rr = ro4[(size_t)ii * O4];
        const float4 mw = mu4[(size_t)ii * O4];
        float4 sg;
        sg.x = log1pf(__expf(rr.x));
        sg.y = log1pf(__expf(rr.y));
        sg.z = log1pf(__expf(rr.z));
        sg.w = log1pf(__expf(rr.w));
#pragma unroll
        for (int k = 0; k < 4; k++) {
            const int lb = g + 2 * k;
            const float xr = xs[lb][ii];
            acc[k].x = fmaf(xr, fmaf(ev[k].x, sg.x, mw.x), acc[k].x);
            acc[k].y = fmaf(xr, fmaf(ev[k].y, sg.y, mw.y), acc[k].y);
            acc[k].z = fmaf(xr, fmaf(ev[k].z, sg.z, mw.z), acc[k].z);
            acc[k].w = fmaf(xr, fmaf(ev[k].w, sg.w, mw.w), acc[k].w);
        }
    }

    // ---- s==0 blocks fold in the bias term ----
    if (s == 0) {
        const float4 rb = reinterpret_cast<const float4*>(ro_bias)[oc];
        const float4 mb = reinterpret_cast<const float4*>(mu_bias)[oc];
        float4 sb;
        sb.x = log1pf(__expf(rb.x));
        sb.y = log1pf(__expf(rb.y));
        sb.z = log1pf(__expf(rb.z));
        sb.w = log1pf(__expf(rb.w));
#pragma unroll
        for (int k = 0; k < 4; k++) {
            const int lb = g + 2 * k;
            const float4 eb = reinterpret_cast<const float4*>(eps_bias)
                                  [(size_t)(b0 + lb) * O4 + oc];
            acc[k].x = fmaf(eb.x, sb.x, acc[k].x + mb.x);
            acc[k].y = fmaf(eb.y, sb.y, acc[k].y + mb.y);
            acc[k].z = fmaf(eb.z, sb.z, acc[k].z + mb.z);
            acc[k].w = fmaf(eb.w, sb.w, acc[k].w + mb.w);
        }
    }

    // ---- write partials P[s][b][o], then signal arrival ----
    float4* Pbase = reinterpret_cast<float4*>(g_partial);
#pragma unroll
    for (int k = 0; k < 4; k++) {
        const int lb = g + 2 * k;
        Pbase[((size_t)s * BB + b0 + lb) * O4 + oc] = acc[k];
    }
    __threadfence();                      // release own partial stores
    __syncthreads();                      // all threads fenced
    if (t == 0)
        atomicAdd(&g_count[bg * OTG + z], 1);
}

// ---------------------------------------------------------------------------
// Launch. Input order (metadata): x, mu, ro, mu_bias, ro_bias, eps, eps_bias
// ---------------------------------------------------------------------------
extern "C" void kernel_launch(void* const* d_in, const int* in_sizes, int n_in,
                              void* d_out, int out_size) {
    const float* x        = (const float*)d_in[0];
    const float* mu       = (const float*)d_in[1];
    const float* ro       = (const float*)d_in[2];
    const float* mu_bias  = (const float*)d_in[3];
    const float* ro_bias  = (const float*)d_in[4];
    const float* eps      = (const float*)d_in[5];
    const float* eps_bias = (const float*)d_in[6];
    float* out = (float*)d_out;

    // One kernel: 1024 producers + 1024 spin-wait reducers, 128 threads, occ 7
    fused_kernel<<<NMAIN + NRED, 128>>>(x, mu, ro, eps,
                                        mu_bias, ro_bias, eps_bias, out);
}